// round 2
// baseline (speedup 1.0000x reference)
#include <cuda_runtime.h>
#include <cuda_bf16.h>

#define NB 16
#define HH 512
#define WW 512
#define PLANE (HH * WW)
#define TOTAL (NB * PLANE)

// Ping-pong scratch (allocation-free: __device__ globals).
// disp stored interleaved: .x = channel0 (y-displacement), .y = channel1 (x-displacement)
__device__ float2 g_dispA[TOTAL];
__device__ float2 g_dispB[TOTAL];
__device__ float  g_ldA[TOTAL];
__device__ float  g_ldB[TOTAL];

__device__ __forceinline__ float2 bilin2(const float2* __restrict__ plane, float sy, float sx) {
    float fy0 = floorf(sy), fx0 = floorf(sx);
    float wy = sy - fy0, wx = sx - fx0;
    int y0 = (int)fy0, x0 = (int)fx0;
    int y1 = y0 + 1, x1 = x0 + 1;
    bool vy0 = (y0 >= 0) & (y0 < HH);
    bool vy1 = (y1 >= 0) & (y1 < HH);
    bool vx0 = (x0 >= 0) & (x0 < WW);
    bool vx1 = (x1 >= 0) & (x1 < WW);
    // issue the (up to) 4 loads early, back-to-back
    float2 v00 = make_float2(0.f, 0.f), v01 = v00, v10 = v00, v11 = v00;
    if (vy0 & vx0) v00 = plane[y0 * WW + x0];
    if (vy0 & vx1) v01 = plane[y0 * WW + x1];
    if (vy1 & vx0) v10 = plane[y1 * WW + x0];
    if (vy1 & vx1) v11 = plane[y1 * WW + x1];
    float w00 = (1.f - wx) * (1.f - wy);
    float w01 = wx * (1.f - wy);
    float w10 = (1.f - wx) * wy;
    float w11 = wx * wy;
    return make_float2(v00.x * w00 + v01.x * w01 + v10.x * w10 + v11.x * w11,
                       v00.y * w00 + v01.y * w01 + v10.y * w10 + v11.y * w11);
}

__device__ __forceinline__ float bilin1(const float* __restrict__ plane, float sy, float sx) {
    float fy0 = floorf(sy), fx0 = floorf(sx);
    float wy = sy - fy0, wx = sx - fx0;
    int y0 = (int)fy0, x0 = (int)fx0;
    int y1 = y0 + 1, x1 = x0 + 1;
    bool vy0 = (y0 >= 0) & (y0 < HH);
    bool vy1 = (y1 >= 0) & (y1 < HH);
    bool vx0 = (x0 >= 0) & (x0 < WW);
    bool vx1 = (x1 >= 0) & (x1 < WW);
    float v00 = 0.f, v01 = 0.f, v10 = 0.f, v11 = 0.f;
    if (vy0 & vx0) v00 = plane[y0 * WW + x0];
    if (vy0 & vx1) v01 = plane[y0 * WW + x1];
    if (vy1 & vx0) v10 = plane[y1 * WW + x0];
    if (vy1 & vx1) v11 = plane[y1 * WW + x1];
    float w00 = (1.f - wx) * (1.f - wy);
    float w01 = wx * (1.f - wy);
    float w10 = (1.f - wx) * wy;
    float w11 = wx * wy;
    return v00 * w00 + v01 * w01 + v10 * w10 + v11 * w11;
}

// Init: disp0 = eps*vel (interleave channels), ldjac0 via Sobel Jacobian + 4-term trace series.
__global__ void __launch_bounds__(256) init_kernel(const float* __restrict__ vel) {
    int idx = blockIdx.x * blockDim.x + threadIdx.x;
    if (idx >= TOTAL) return;
    int n = idx >> 18;            // / PLANE (2^18)
    int rem = idx & (PLANE - 1);
    int y = rem >> 9;             // / WW
    int x = rem & (WW - 1);

    const float* v0 = vel + (size_t)(2 * n) * PLANE;      // channel 0 (y-vel)
    const float* v1 = v0 + PLANE;                         // channel 1 (x-vel)

    const float eps = 0.0078125f;  // 2^-7
    float vy = v0[rem], vx = v1[rem];
    g_dispA[idx] = make_float2(eps * vy, eps * vx);

    // replicate padding: clamp neighbor indices
    int ym = max(y - 1, 0), yp = min(y + 1, HH - 1);
    int xm = max(x - 1, 0), xp = min(x + 1, WW - 1);

    // channel 0 (vel_y): J00 = d/dy, J01 = d/dx  (Sobel correlation, *0.125)
    float a00 = v0[ym * WW + xm], a01 = v0[ym * WW + x], a02 = v0[ym * WW + xp];
    float a10 = v0[y  * WW + xm],                          a12 = v0[y  * WW + xp];
    float a20 = v0[yp * WW + xm], a21 = v0[yp * WW + x], a22 = v0[yp * WW + xp];
    float J00 = 0.125f * ((a20 + 2.f * a21 + a22) - (a00 + 2.f * a01 + a02));
    float J01 = 0.125f * ((a02 + 2.f * a12 + a22) - (a00 + 2.f * a10 + a20));

    // channel 1 (vel_x): J10 = d/dy, J11 = d/dx
    float b00 = v1[ym * WW + xm], b01 = v1[ym * WW + x], b02 = v1[ym * WW + xp];
    float b10 = v1[y  * WW + xm],                          b12 = v1[y  * WW + xp];
    float b20 = v1[yp * WW + xm], b21 = v1[yp * WW + x], b22 = v1[yp * WW + xp];
    float J10 = 0.125f * ((b20 + 2.f * b21 + b22) - (b00 + 2.f * b01 + b02));
    float J11 = 0.125f * ((b02 + 2.f * b12 + b22) - (b00 + 2.f * b10 + b20));

    // logdet(I + eps*J) series: ld = -sum_{n=1..4} (-eps)^n tr(J^n)/n
    // power sums via trace/det recurrence: s_n = t*s_{n-1} - d*s_{n-2}
    float t = J00 + J11;
    float d = J00 * J11 - J01 * J10;
    float s1 = t;
    float s2 = t * t - 2.f * d;
    float s3 = t * s2 - d * s1;
    float s4 = t * s3 - d * s2;
    const float e2 = eps * eps, e3 = e2 * eps, e4 = e3 * eps;
    g_ldA[idx] = eps * s1 - 0.5f * e2 * s2 + (e3 * (1.f / 3.f)) * s3 - 0.25f * e4 * s4;
}

// One squaring step, fused:
//   disp_new = disp_old + warp(disp_old, disp_old)
//   ldjac_new = ldjac_old + warp(ldjac_old, disp_new)
// Templated so ping-pong pointers are compile-time constants.
template <bool SRC_A, bool FINAL>
__global__ void __launch_bounds__(256) step_kernel(float* __restrict__ out_disp,
                                                   float* __restrict__ out_ld) {
    int idx = blockIdx.x * blockDim.x + threadIdx.x;
    if (idx >= TOTAL) return;
    int n = idx >> 18;
    int rem = idx & (PLANE - 1);
    int y = rem >> 9;
    int x = rem & (WW - 1);

    const float2* __restrict__ dp = (SRC_A ? g_dispA : g_dispB) + (size_t)n * PLANE;
    const float*  __restrict__ lp = (SRC_A ? g_ldA   : g_ldB)   + (size_t)n * PLANE;

    const float SC = (float)HH / (float)(HH - 1);  // H == W == 512

    float2 d = dp[rem];
    float sy = (y + d.x) * SC - 0.5f;
    float sx = (x + d.y) * SC - 0.5f;
    float2 s = bilin2(dp, sy, sx);
    float2 dn = make_float2(d.x + s.x, d.y + s.y);

    float sy2 = (y + dn.x) * SC - 0.5f;
    float sx2 = (x + dn.y) * SC - 0.5f;
    float ln = lp[rem] + bilin1(lp, sy2, sx2);

    if (FINAL) {
        // planar output: disp [N,2,H,W] then ldjac [N,1,H,W]
        out_disp[(size_t)(2 * n) * PLANE + rem]     = dn.x;
        out_disp[(size_t)(2 * n + 1) * PLANE + rem] = dn.y;
        out_ld[(size_t)n * PLANE + rem]             = ln;
    } else {
        (SRC_A ? g_dispB : g_dispA)[idx] = dn;
        (SRC_A ? g_ldB   : g_ldA)[idx]   = ln;
    }
}

extern "C" void kernel_launch(void* const* d_in, const int* in_sizes, int n_in,
                              void* d_out, int out_size) {
    const float* vel = (const float*)d_in[0];
    float* out = (float*)d_out;
    float* out_disp = out;
    float* out_ld = out + (size_t)NB * 2 * PLANE;

    const int threads = 256;
    const int blocks = (TOTAL + threads - 1) / threads;

    init_kernel<<<blocks, threads>>>(vel);
    // 7 steps: A->B, B->A, A->B, B->A, A->B, B->A, A->out
    step_kernel<true,  false><<<blocks, threads>>>(out_disp, out_ld);
    step_kernel<false, false><<<blocks, threads>>>(out_disp, out_ld);
    step_kernel<true,  false><<<blocks, threads>>>(out_disp, out_ld);
    step_kernel<false, false><<<blocks, threads>>>(out_disp, out_ld);
    step_kernel<true,  false><<<blocks, threads>>>(out_disp, out_ld);
    step_kernel<false, false><<<blocks, threads>>>(out_disp, out_ld);
    step_kernel<true,  true ><<<blocks, threads>>>(out_disp, out_ld);
}

// round 3
// speedup vs baseline: 1.3176x; 1.3176x over previous
#include <cuda_runtime.h>
#include <cuda_bf16.h>

#define NB 16
#define HH 512
#define WW 512
#define PLANE (HH * WW)
#define TOTAL (NB * PLANE)

// Ping-pong scratch (allocation-free: __device__ globals).
// disp stored interleaved: .x = channel0 (y-displacement), .y = channel1 (x-displacement)
__device__ float2 g_dispA[TOTAL];
__device__ float2 g_dispB[TOTAL];
__device__ float  g_ldA[TOTAL];
__device__ float  g_ldB[TOTAL];

__device__ __forceinline__ float2 bilin2(const float2* __restrict__ plane, float sy, float sx) {
    float fy0 = floorf(sy), fx0 = floorf(sx);
    float wy = sy - fy0, wx = sx - fx0;
    int y0 = (int)fy0, x0 = (int)fx0;
    int y1 = y0 + 1, x1 = x0 + 1;
    bool vy0 = (y0 >= 0) & (y0 < HH);
    bool vy1 = (y1 >= 0) & (y1 < HH);
    bool vx0 = (x0 >= 0) & (x0 < WW);
    bool vx1 = (x1 >= 0) & (x1 < WW);
    float2 v00 = make_float2(0.f, 0.f), v01 = v00, v10 = v00, v11 = v00;
    int base = y0 * WW + x0;
    if (vy0 & vx0) v00 = plane[base];
    if (vy0 & vx1) v01 = plane[base + 1];
    if (vy1 & vx0) v10 = plane[base + WW];
    if (vy1 & vx1) v11 = plane[base + WW + 1];
    float w00 = (1.f - wx) * (1.f - wy);
    float w01 = wx * (1.f - wy);
    float w10 = (1.f - wx) * wy;
    float w11 = wx * wy;
    return make_float2(v00.x * w00 + v01.x * w01 + v10.x * w10 + v11.x * w11,
                       v00.y * w00 + v01.y * w01 + v10.y * w10 + v11.y * w11);
}

__device__ __forceinline__ float bilin1(const float* __restrict__ plane, float sy, float sx) {
    float fy0 = floorf(sy), fx0 = floorf(sx);
    float wy = sy - fy0, wx = sx - fx0;
    int y0 = (int)fy0, x0 = (int)fx0;
    int y1 = y0 + 1, x1 = x0 + 1;
    bool vy0 = (y0 >= 0) & (y0 < HH);
    bool vy1 = (y1 >= 0) & (y1 < HH);
    bool vx0 = (x0 >= 0) & (x0 < WW);
    bool vx1 = (x1 >= 0) & (x1 < WW);
    float v00 = 0.f, v01 = 0.f, v10 = 0.f, v11 = 0.f;
    int base = y0 * WW + x0;
    if (vy0 & vx0) v00 = plane[base];
    if (vy0 & vx1) v01 = plane[base + 1];
    if (vy1 & vx0) v10 = plane[base + WW];
    if (vy1 & vx1) v11 = plane[base + WW + 1];
    float w00 = (1.f - wx) * (1.f - wy);
    float w01 = wx * (1.f - wy);
    float w10 = (1.f - wx) * wy;
    float w11 = wx * wy;
    return v00 * w00 + v01 * w01 + v10 * w10 + v11 * w11;
}

// logdet(I + eps*J) 4-term trace series via power-sum recurrence.
__device__ __forceinline__ float logdet_series(float J00, float J01, float J10, float J11) {
    const float eps = 0.0078125f;  // 2^-7
    float t = J00 + J11;
    float d = J00 * J11 - J01 * J10;
    float s2 = t * t - 2.f * d;
    float s3 = t * s2 - d * t;
    float s4 = t * s3 - d * s2;
    const float e2 = eps * eps, e3 = e2 * eps, e4 = e3 * eps;
    return eps * t - 0.5f * e2 * s2 + (e3 * (1.f / 3.f)) * s3 - 0.25f * e4 * s4;
}

// Init (2 pixels/thread): disp0 = eps*vel, ldjac0 from Sobel Jacobian.
__global__ void __launch_bounds__(256) init_kernel(const float* __restrict__ vel) {
    int tid = blockIdx.x * blockDim.x + threadIdx.x;
    if (tid >= TOTAL / 2) return;
    int idx = tid << 1;
    int n = idx >> 18;            // / PLANE (2^18)
    int rem = idx & (PLANE - 1);
    int y = rem >> 9;             // / WW
    int x = rem & (WW - 1);       // even

    const float* v0 = vel + (size_t)(2 * n) * PLANE;      // channel 0 (y-vel)
    const float* v1 = v0 + PLANE;                         // channel 1 (x-vel)

    const float eps = 0.0078125f;  // 2^-7

    // replicate padding: clamp rows; columns c0..c3 cover both pixels' stencils
    int ym = max(y - 1, 0), yp = min(y + 1, HH - 1);
    int c0 = max(x - 1, 0), c1 = x, c2 = x + 1, c3 = min(x + 2, WW - 1);
    int rm = ym * WW, rc = y * WW, rp = yp * WW;

    // channel 0 rows (4 cols x 3 rows)
    float a0m = v0[rm + c0], a1m = v0[rm + c1], a2m = v0[rm + c2], a3m = v0[rm + c3];
    float a0c = v0[rc + c0], a1c = v0[rc + c1], a2c = v0[rc + c2], a3c = v0[rc + c3];
    float a0p = v0[rp + c0], a1p = v0[rp + c1], a2p = v0[rp + c2], a3p = v0[rp + c3];
    // channel 1 rows
    float b0m = v1[rm + c0], b1m = v1[rm + c1], b2m = v1[rm + c2], b3m = v1[rm + c3];
    float b0c = v1[rc + c0], b1c = v1[rc + c1], b2c = v1[rc + c2], b3c = v1[rc + c3];
    float b0p = v1[rp + c0], b1p = v1[rp + c1], b2p = v1[rp + c2], b3p = v1[rp + c3];

    // disp0 (center values are a1c/b1c and a2c/b2c)
    float4 d0 = make_float4(eps * a1c, eps * b1c, eps * a2c, eps * b2c);
    *(float4*)(g_dispA + idx) = d0;

    // pixel 0 Jacobian (cols c0,c1,c2)
    float J00a = 0.125f * ((a0p + 2.f * a1p + a2p) - (a0m + 2.f * a1m + a2m));
    float J01a = 0.125f * ((a2m + 2.f * a2c + a2p) - (a0m + 2.f * a0c + a0p));
    float J10a = 0.125f * ((b0p + 2.f * b1p + b2p) - (b0m + 2.f * b1m + b2m));
    float J11a = 0.125f * ((b2m + 2.f * b2c + b2p) - (b0m + 2.f * b0c + b0p));
    // pixel 1 Jacobian (cols c1,c2,c3)
    float J00b = 0.125f * ((a1p + 2.f * a2p + a3p) - (a1m + 2.f * a2m + a3m));
    float J01b = 0.125f * ((a3m + 2.f * a3c + a3p) - (a1m + 2.f * a1c + a1p));
    float J10b = 0.125f * ((b1p + 2.f * b2p + b3p) - (b1m + 2.f * b2m + b3m));
    float J11b = 0.125f * ((b3m + 2.f * b3c + b3p) - (b1m + 2.f * b1c + b1p));

    float2 ld = make_float2(logdet_series(J00a, J01a, J10a, J11a),
                            logdet_series(J00b, J01b, J10b, J11b));
    *(float2*)(g_ldA + idx) = ld;
}

// One squaring step, fused, 2 pixels/thread:
//   disp_new = disp_old + warp(disp_old, disp_old)
//   ldjac_new = ldjac_old + warp(ldjac_old, disp_new)
template <bool SRC_A, bool FINAL>
__global__ void __launch_bounds__(256) step_kernel(float* __restrict__ out_disp,
                                                   float* __restrict__ out_ld) {
    int tid = blockIdx.x * blockDim.x + threadIdx.x;
    if (tid >= TOTAL / 2) return;
    int idx = tid << 1;
    int n = idx >> 18;
    int rem = idx & (PLANE - 1);
    int y = rem >> 9;
    int x = rem & (WW - 1);   // even

    const float2* __restrict__ dp = (SRC_A ? g_dispA : g_dispB) + (size_t)n * PLANE;
    const float*  __restrict__ lp = (SRC_A ? g_ldA   : g_ldB)   + (size_t)n * PLANE;

    const float SC = (float)HH / (float)(HH - 1);  // H == W == 512

    float4 dc = *(const float4*)(dp + rem);   // pixel0=(x,y comps dc.x,dc.y), pixel1=(dc.z,dc.w)
    float2 lc = *(const float2*)(lp + rem);

    float fy = (float)y, fx = (float)x;
    // pixel 0 self-warp
    float sy0 = (fy + dc.x) * SC - 0.5f;
    float sx0 = (fx + dc.y) * SC - 0.5f;
    // pixel 1 self-warp
    float sy1 = (fy + dc.z) * SC - 0.5f;
    float sx1 = (fx + 1.f + dc.w) * SC - 0.5f;

    float2 s0 = bilin2(dp, sy0, sx0);
    float2 s1 = bilin2(dp, sy1, sx1);

    float dn0x = dc.x + s0.x, dn0y = dc.y + s0.y;
    float dn1x = dc.z + s1.x, dn1y = dc.w + s1.y;

    float l0 = lc.x + bilin1(lp, (fy + dn0x) * SC - 0.5f, (fx + dn0y) * SC - 0.5f);
    float l1 = lc.y + bilin1(lp, (fy + dn1x) * SC - 0.5f, (fx + 1.f + dn1y) * SC - 0.5f);

    if (FINAL) {
        // planar output: disp [N,2,H,W] then ldjac [N,1,H,W]
        *(float2*)(out_disp + (size_t)(2 * n) * PLANE + rem)     = make_float2(dn0x, dn1x);
        *(float2*)(out_disp + (size_t)(2 * n + 1) * PLANE + rem) = make_float2(dn0y, dn1y);
        *(float2*)(out_ld + (size_t)n * PLANE + rem)             = make_float2(l0, l1);
    } else {
        float2* __restrict__ ddst = SRC_A ? g_dispB : g_dispA;
        float*  __restrict__ ldst = SRC_A ? g_ldB   : g_ldA;
        *(float4*)(ddst + idx) = make_float4(dn0x, dn0y, dn1x, dn1y);
        *(float2*)(ldst + idx) = make_float2(l0, l1);
    }
}

extern "C" void kernel_launch(void* const* d_in, const int* in_sizes, int n_in,
                              void* d_out, int out_size) {
    const float* vel = (const float*)d_in[0];
    float* out = (float*)d_out;
    float* out_disp = out;
    float* out_ld = out + (size_t)NB * 2 * PLANE;

    const int threads = 256;
    const int blocks = (TOTAL / 2 + threads - 1) / threads;

    init_kernel<<<blocks, threads>>>(vel);
    // 7 steps: A->B, B->A, A->B, B->A, A->B, B->A, A->out
    step_kernel<true,  false><<<blocks, threads>>>(out_disp, out_ld);
    step_kernel<false, false><<<blocks, threads>>>(out_disp, out_ld);
    step_kernel<true,  false><<<blocks, threads>>>(out_disp, out_ld);
    step_kernel<false, false><<<blocks, threads>>>(out_disp, out_ld);
    step_kernel<true,  false><<<blocks, threads>>>(out_disp, out_ld);
    step_kernel<false, false><<<blocks, threads>>>(out_disp, out_ld);
    step_kernel<true,  true ><<<blocks, threads>>>(out_disp, out_ld);
}